// round 13
// baseline (speedup 1.0000x reference)
#include <cuda_runtime.h>
#include <cuda_fp16.h>
#include <cstdint>
#include <cstddef>

#define BB 8
#define CC 256
#define NNDIM 1024
#define KDIM 16
#define CQ 64

// ---------------- scratch (device globals; no allocation allowed) ----------------
__device__ float g_wcat[384 * 256];                              // concat q/k/v weights
__device__ float g_xT[(size_t)BB * KDIM * CC * NNDIM];           // [b][k][c][n]
__device__ float g_xq[(size_t)BB * KDIM * CQ * NNDIM];           // [z][cq][n]
__device__ float g_xk[(size_t)BB * KDIM * CQ * NNDIM];           // [z][cq][n]
__device__ float g_xq2[(size_t)BB * KDIM * (CQ/2) * NNDIM * 2];  // [z][cq/2][n] (hi2,lo2) fp16x2
__device__ float g_xk2[(size_t)BB * KDIM * (CQ/2) * NNDIM * 2];  // [z][cq/2][n]
__device__ float g_xv[(size_t)BB * KDIM * CC * NNDIM];           // [b][k][c][n]
__device__ float g_S [(size_t)BB * KDIM * NNDIM * NNDIM];        // S^T pre-renorm fp32 [z][m][n]
__device__ __half g_Sh[(size_t)BB * KDIM * NNDIM * NNDIM];       // S^T renormalized fp16 [z][m][n]
__device__ float g_d [(size_t)BB * KDIM * CC * NNDIM];           // x - x_r
__device__ float g_t [(size_t)BB * CC * KDIM * NNDIM];           // t proj [b][c][k][n]
__device__ float g_a [CC];
__device__ float g_b2[CC];

__device__ __forceinline__ uint32_t f2tf32(float f) {
    uint32_t u;
    asm("cvt.rna.tf32.f32 %0, %1;" : "=r"(u) : "f"(f));
    return u;
}

__device__ __forceinline__ void mma_tf32(float c[4], const uint32_t a[4], const uint32_t b[2]) {
    asm volatile("mma.sync.aligned.m16n8k8.row.col.f32.tf32.tf32.f32 "
                 "{%0,%1,%2,%3}, {%4,%5,%6,%7}, {%8,%9}, {%0,%1,%2,%3};"
                 : "+f"(c[0]), "+f"(c[1]), "+f"(c[2]), "+f"(c[3])
                 : "r"(a[0]), "r"(a[1]), "r"(a[2]), "r"(a[3]), "r"(b[0]), "r"(b[1]));
}

__device__ __forceinline__ void mma_f16(float c[4], const uint32_t a[4], const uint32_t b[2]) {
    asm volatile("mma.sync.aligned.m16n8k16.row.col.f32.f16.f16.f32 "
                 "{%0,%1,%2,%3}, {%4,%5,%6,%7}, {%8,%9}, {%0,%1,%2,%3};"
                 : "+f"(c[0]), "+f"(c[1]), "+f"(c[2]), "+f"(c[3])
                 : "r"(a[0]), "r"(a[1]), "r"(a[2]), "r"(a[3]), "r"(b[0]), "r"(b[1]));
}

// ---------------- kernel 0: concat weights ----------------
__global__ void k_concat(const float* __restrict__ q_w, const float* __restrict__ k_w,
                         const float* __restrict__ v_w) {
    int i = blockIdx.x * 256 + threadIdx.x;
    if (i >= 384 * 256) return;
    int o = i >> 8;
    float v;
    if (o < 64)        v = q_w[i];
    else if (o < 128)  v = k_w[i - 64 * 256];
    else               v = v_w[i - 128 * 256];
    g_wcat[i] = v;
}

// ---------------- kernel 1: transpose x [b,c,n,k] -> xT [b,k,c,n] ----------------
__global__ void k_transpose_x(const float* __restrict__ x) {
    __shared__ float ts[16][68];
    int bc = blockIdx.x;
    int b = bc >> 8, c = bc & 255;
    int t = threadIdx.x;
    int nn = t >> 2, kg = (t & 3) << 2;
    int kk = t >> 4, n4 = (t & 15) << 2;
    for (int n0 = 0; n0 < NNDIM; n0 += 64) {
        float4 v = *(const float4*)&x[(((size_t)bc * NNDIM) + n0 + nn) * KDIM + kg];
        ts[kg + 0][nn] = v.x; ts[kg + 1][nn] = v.y; ts[kg + 2][nn] = v.z; ts[kg + 3][nn] = v.w;
        __syncthreads();
        float4 o = make_float4(ts[kk][n4], ts[kk][n4 + 1], ts[kk][n4 + 2], ts[kk][n4 + 3]);
        *(float4*)&g_xT[(((size_t)(b * KDIM + kk) * CC + c) * NNDIM) + n0 + n4] = o;
        __syncthreads();
    }
}

// ---------------- unified tf32 mma.sync tile GEMM (proj / xr / tproj) ----------------
// MODE 0: xr   : A=g_xv[z],  B=g_Sh^T[z] fp16 (K-major direct). K=1024. epi: d = xT - acc
// MODE 1: proj : A=g_wcat,   B=g_xT[z] (transpose-load). K=256. epi: q/k/v(+bias)
// MODE 2: tproj: A=t_w,      B=g_d[z]  (transpose-load). K=256. epi: +bias -> g_t
template<int MODE>
__global__ __launch_bounds__(256) void k_mma(const float* __restrict__ A_ext,
                                             const float* __restrict__ bias) {
    __shared__ uint32_t As[128][36];
    __shared__ uint32_t Bs[128][36];

    const int t = threadIdx.x;
    const int wid = t >> 5, lane = t & 31;
    const int gr = lane >> 2, tg = lane & 3;
    const int wm = (wid >> 2) * 64, wn = (wid & 3) * 32;
    const int z  = blockIdx.z;
    const int n0 = blockIdx.x << 7;
    const int m0 = blockIdx.y << 7;
    const int KTOT = (MODE == 0) ? 1024 : 256;
    const int NC = KTOT / 32;

    const float* Ap;
    const float* Bp = nullptr;
    const __half* Bh = nullptr;
    if (MODE == 0) {
        Ap = g_xv + ((size_t)z * CC + m0) * NNDIM;
        Bh = g_Sh + (size_t)z * NNDIM * NNDIM + (size_t)n0 * NNDIM;
    } else if (MODE == 1) {
        Ap = g_wcat + (size_t)m0 * 256;
        Bp = g_xT + (size_t)z * CC * NNDIM + n0;
    } else {
        Ap = A_ext + (size_t)m0 * 256;
        Bp = g_d + (size_t)z * CC * NNDIM + n0;
    }
    const int lda = (MODE == 0) ? NNDIM : 256;

    float ra[16], rb[16];
    const int arow = t >> 1, ah = (t & 1) << 4;
    const int bc_ = t >> 3, bn4 = (t & 7) << 4;

    auto loadA = [&](int k0) {
#pragma unroll
        for (int j = 0; j < 4; j++) {
            float4 v = *(const float4*)&Ap[(size_t)arow * lda + k0 + ah + j * 4];
            ra[j * 4 + 0] = v.x; ra[j * 4 + 1] = v.y; ra[j * 4 + 2] = v.z; ra[j * 4 + 3] = v.w;
        }
    };
    auto loadB = [&](int k0) {
        if (MODE == 0) {
            // 16 halves = 32 bytes = TWO uint4 loads
            uint4 u0 = *(const uint4*)&Bh[(size_t)arow * NNDIM + k0 + ah];
            uint4 u1 = *(const uint4*)&Bh[(size_t)arow * NNDIM + k0 + ah + 8];
            const __half2* h0 = (const __half2*)&u0;
            const __half2* h1 = (const __half2*)&u1;
#pragma unroll
            for (int j = 0; j < 4; j++) {
                float2 f = __half22float2(h0[j]);
                rb[2 * j] = f.x; rb[2 * j + 1] = f.y;
            }
#pragma unroll
            for (int j = 0; j < 4; j++) {
                float2 f = __half22float2(h1[j]);
                rb[8 + 2 * j] = f.x; rb[8 + 2 * j + 1] = f.y;
            }
        } else {
#pragma unroll
            for (int j = 0; j < 4; j++) {
                float4 v = *(const float4*)&Bp[(size_t)(k0 + bc_) * NNDIM + bn4 + j * 4];
                rb[j * 4 + 0] = v.x; rb[j * 4 + 1] = v.y; rb[j * 4 + 2] = v.z; rb[j * 4 + 3] = v.w;
            }
        }
    };
    auto storeAB = [&]() {
#pragma unroll
        for (int j = 0; j < 16; j++) As[arow][ah + j] = f2tf32(ra[j]);
        if (MODE == 0) {
#pragma unroll
            for (int j = 0; j < 16; j++) Bs[arow][ah + j] = f2tf32(rb[j]);
        } else {
#pragma unroll
            for (int j = 0; j < 16; j++) Bs[bn4 + j][bc_] = f2tf32(rb[j]);
        }
    };

    float acc[4][4][4] = {};
    loadA(0); loadB(0);
    for (int c = 0; c < NC; c++) {
        __syncthreads();
        storeAB();
        __syncthreads();
        if (c + 1 < NC) { loadA((c + 1) * 32); loadB((c + 1) * 32); }
#pragma unroll
        for (int ks = 0; ks < 4; ks++) {
            int k0 = ks * 8;
            uint32_t af[4][4], bf[4][2];
#pragma unroll
            for (int mt = 0; mt < 4; mt++) {
                int r = wm + mt * 16 + gr;
                af[mt][0] = As[r][k0 + tg];
                af[mt][1] = As[r + 8][k0 + tg];
                af[mt][2] = As[r][k0 + tg + 4];
                af[mt][3] = As[r + 8][k0 + tg + 4];
            }
#pragma unroll
            for (int nt = 0; nt < 4; nt++) {
                int r = wn + nt * 8 + gr;
                bf[nt][0] = Bs[r][k0 + tg];
                bf[nt][1] = Bs[r][k0 + tg + 4];
            }
#pragma unroll
            for (int mt = 0; mt < 4; mt++)
#pragma unroll
                for (int nt = 0; nt < 4; nt++)
                    mma_tf32(acc[mt][nt], af[mt], bf[nt]);
        }
    }

#pragma unroll
    for (int mt = 0; mt < 4; mt++) {
#pragma unroll
        for (int nt = 0; nt < 4; nt++) {
#pragma unroll
            for (int h = 0; h < 2; h++) {
                int row = m0 + wm + mt * 16 + gr + h * 8;
                int col = n0 + wn + nt * 8 + 2 * tg;
                float v0 = acc[mt][nt][h * 2 + 0];
                float v1 = acc[mt][nt][h * 2 + 1];
                if (MODE == 0) {
                    size_t idx = ((size_t)z * CC + row) * NNDIM + col;
                    float2 xv = *(const float2*)&g_xT[idx];
                    *(float2*)&g_d[idx] = make_float2(xv.x - v0, xv.y - v1);
                } else if (MODE == 1) {
                    float2 r2 = make_float2(v0, v1);
                    if (row < 64) {
                        *(float2*)&g_xq[((size_t)z * CQ + row) * NNDIM + col] = r2;
                    } else if (row < 128) {
                        *(float2*)&g_xk[((size_t)z * CQ + row - 64) * NNDIM + col] = r2;
                    } else {
                        float bb = bias[row - 128];
                        *(float2*)&g_xv[((size_t)z * CC + row - 128) * NNDIM + col] =
                            make_float2(v0 + bb, v1 + bb);
                    }
                } else {
                    float bb = bias[row];
                    int b = z >> 4, kb = z & 15;
                    *(float2*)&g_t[(((size_t)(b * CC + row)) * KDIM + kb) * NNDIM + col] =
                        make_float2(v0 + bb, v1 + bb);
                }
            }
        }
    }
}

// ---------------- kernel 2b: split q/k into packed fp16x2 (hi,lo) channel pairs ----------------
__global__ void k_split() {
    int bc = blockIdx.x;            // z*32 + c2
    int z = bc >> 5, c2 = bc & 31;
    int t = threadIdx.x;
    size_t ibase = ((size_t)z * CQ + 2 * c2) * NNDIM;
    size_t obase = ((size_t)z * 32 + c2) * NNDIM;
#pragma unroll
    for (int s = 0; s < 2; s++) {
        const float* src = s ? g_xk : g_xq;
        float2* dst = (float2*)(s ? g_xk2 : g_xq2) + obase;
        float4 a = *(const float4*)&src[ibase + t * 4];
        float4 b = *(const float4*)&src[ibase + NNDIM + t * 4];
        const float* ap = &a.x;
        const float* bp = &b.x;
#pragma unroll
        for (int j = 0; j < 4; j++) {
            float x = ap[j], y = bp[j];
            __half hx = __float2half_rn(x), hy = __float2half_rn(y);
            float lx = x - __half2float(hx), ly = y - __half2float(hy);
            __half2 h2 = __halves2half2(hx, hy);
            __half2 l2 = __halves2half2(__float2half_rn(lx), __float2half_rn(ly));
            float2 o;
            o.x = __uint_as_float(*(uint32_t*)&h2);
            o.y = __uint_as_float(*(uint32_t*)&l2);
            dst[t * 4 + j] = o;
        }
    }
}

// ---------------- kernel 3: energy (split-fp16 mma) + softmax, writes S^T fp32 [z][m][n] ----------------
__global__ __launch_bounds__(512) void k_energy_v3() {
    __shared__ float redmax[32][9];
    __shared__ float redsum[32][9];
    int z  = blockIdx.y;
    int n0 = blockIdx.x << 5;
    int t  = threadIdx.x;
    int wid = t >> 5, lane = t & 31;
    int gr = lane >> 2, tg = lane & 3;
    int wn2 = wid >> 3;
    int wm8 = wid & 7;
    int r0 = wn2 * 16 + gr;
    int nrow = n0 + r0;
    int mb = wm8 << 7;
    const float2* q2 = (const float2*)g_xq2 + (size_t)z * 32 * NNDIM;
    const float2* k2 = (const float2*)g_xk2 + (size_t)z * 32 * NNDIM;

    float acc[16][4] = {};
#pragma unroll
    for (int ks = 0; ks < 4; ks++) {
        int p0 = ks << 3;
        float2 A0 = q2[(size_t)(p0 + tg) * NNDIM + nrow];
        float2 A1 = q2[(size_t)(p0 + tg) * NNDIM + nrow + 8];
        float2 A2 = q2[(size_t)(p0 + tg + 4) * NNDIM + nrow];
        float2 A3 = q2[(size_t)(p0 + tg + 4) * NNDIM + nrow + 8];
        uint32_t ah[4] = {__float_as_uint(A0.x), __float_as_uint(A1.x),
                          __float_as_uint(A2.x), __float_as_uint(A3.x)};
        uint32_t al[4] = {__float_as_uint(A0.y), __float_as_uint(A1.y),
                          __float_as_uint(A2.y), __float_as_uint(A3.y)};
#pragma unroll
        for (int nf = 0; nf < 16; nf++) {
            int m = mb + nf * 8 + gr;
            float2 B0 = k2[(size_t)(p0 + tg) * NNDIM + m];
            float2 B1 = k2[(size_t)(p0 + tg + 4) * NNDIM + m];
            uint32_t bh[2] = {__float_as_uint(B0.x), __float_as_uint(B1.x)};
            uint32_t bl[2] = {__float_as_uint(B0.y), __float_as_uint(B1.y)};
            mma_f16(acc[nf], ah, bh);
            mma_f16(acc[nf], ah, bl);
            mma_f16(acc[nf], al, bh);
        }
    }
    const unsigned FULL = 0xffffffffu;
    float m0 = -1e30f, m1 = -1e30f;
#pragma unroll
    for (int nf = 0; nf < 16; nf++) {
        m0 = fmaxf(m0, fmaxf(acc[nf][0], acc[nf][1]));
        m1 = fmaxf(m1, fmaxf(acc[nf][2], acc[nf][3]));
    }
    m0 = fmaxf(m0, __shfl_xor_sync(FULL, m0, 1));
    m0 = fmaxf(m0, __shfl_xor_sync(FULL, m0, 2));
    m1 = fmaxf(m1, __shfl_xor_sync(FULL, m1, 1));
    m1 = fmaxf(m1, __shfl_xor_sync(FULL, m1, 2));
    if (tg == 0) { redmax[r0][wm8] = m0; redmax[r0 + 8][wm8] = m1; }
    __syncthreads();
    float mx0 = -1e30f, mx1 = -1e30f;
#pragma unroll
    for (int j = 0; j < 8; j++) {
        mx0 = fmaxf(mx0, redmax[r0][j]);
        mx1 = fmaxf(mx1, redmax[r0 + 8][j]);
    }
    float s0 = 0.0f, s1 = 0.0f;
#pragma unroll
    for (int nf = 0; nf < 16; nf++) {
        acc[nf][0] = __expf(acc[nf][0] - mx0);
        acc[nf][1] = __expf(acc[nf][1] - mx0);
        acc[nf][2] = __expf(acc[nf][2] - mx1);
        acc[nf][3] = __expf(acc[nf][3] - mx1);
        s0 += acc[nf][0] + acc[nf][1];
        s1 += acc[nf][2] + acc[nf][3];
    }
    s0 += __shfl_xor_sync(FULL, s0, 1);
    s0 += __shfl_xor_sync(FULL, s0, 2);
    s1 += __shfl_xor_sync(FULL, s1, 1);
    s1 += __shfl_xor_sync(FULL, s1, 2);
    if (tg == 0) { redsum[r0][wm8] = s0; redsum[r0 + 8][wm8] = s1; }
    __syncthreads();
    float sum0 = 0.0f, sum1 = 0.0f;
#pragma unroll
    for (int j = 0; j < 8; j++) {
        sum0 += redsum[r0][j];
        sum1 += redsum[r0 + 8][j];
    }
    float inv0 = 1.0f / sum0, inv1 = 1.0f / sum1;
    float* ST = g_S + (size_t)z * NNDIM * NNDIM;
#pragma unroll
    for (int nf = 0; nf < 16; nf++) {
        int m = mb + nf * 8 + 2 * tg;
        float* c0 = ST + (size_t)m * NNDIM + nrow;
        float* c1 = c0 + NNDIM;
        c0[0] = acc[nf][0] * inv0;
        c1[0] = acc[nf][1] * inv0;
        c0[8] = acc[nf][2] * inv1;
        c1[8] = acc[nf][3] * inv1;
    }
}

// ---------------- kernel 4: cross-K renorm: fp32 in, renormalized fp16 out ----------------
__global__ void k_renorm_cvt() {
    size_t p = (size_t)blockIdx.x * 256 + threadIdx.x;   // < 8 * 262144
    int b = (int)(p >> 18);
    size_t off = (size_t)(p & 262143) << 2;              // 4 floats per thread
    const size_t ks = (size_t)NNDIM * NNDIM;
    size_t base = (size_t)b * KDIM * ks + off;
    float4 v[16];
    float4 s = make_float4(1e-9f, 1e-9f, 1e-9f, 1e-9f);
#pragma unroll
    for (int k = 0; k < 16; k++) {
        v[k] = *(const float4*)&g_S[base + (size_t)k * ks];
        s.x += v[k].x; s.y += v[k].y; s.z += v[k].z; s.w += v[k].w;
    }
    float4 inv = make_float4(1.0f / s.x, 1.0f / s.y, 1.0f / s.z, 1.0f / s.w);
#pragma unroll
    for (int k = 0; k < 16; k++) {
        __half2 h01 = __floats2half2_rn(v[k].x * inv.x, v[k].y * inv.y);
        __half2 h23 = __floats2half2_rn(v[k].z * inv.z, v[k].w * inv.w);
        uint2 o;
        o.x = *(uint32_t*)&h01;
        o.y = *(uint32_t*)&h23;
        *(uint2*)&g_Sh[base + (size_t)k * ks] = o;
    }
}

// ---------------- kernel 7: BN stats per channel ----------------
__global__ void k_stats(const float* __restrict__ gamma, const float* __restrict__ beta) {
    int c = blockIdx.x;
    int t = threadIdx.x;
    float s = 0.0f, sq = 0.0f;
    for (int b = 0; b < BB; b++) {
        const float* base = g_t + ((size_t)(b * CC + c)) * KDIM * NNDIM;
        for (int fl = t; fl < 4096; fl += 256) {
            float4 v = *(const float4*)&base[fl * 4];
            s  += v.x + v.y + v.z + v.w;
            sq += v.x * v.x + v.y * v.y + v.z * v.z + v.w * v.w;
        }
    }
    __shared__ float ss[256], sqq[256];
    ss[t] = s; sqq[t] = sq;
    __syncthreads();
    for (int o = 128; o > 0; o >>= 1) {
        if (t < o) { ss[t] += ss[t + o]; sqq[t] += sqq[t + o]; }
        __syncthreads();
    }
    if (t == 0) {
        const float cnt = 131072.0f;
        float mean = ss[0] / cnt;
        float var  = sqq[0] / cnt - mean * mean;
        float rstd = rsqrtf(var + 1e-5f);
        float a = rstd * gamma[c];
        g_a[c]  = a;
        g_b2[c] = beta[c] - mean * a;
    }
}

// ---------------- kernel 8: out = x + relu(t*a + b2), transpose [k][n]->[n][k] ----------------
__global__ void k_final(const float* __restrict__ x, float* __restrict__ out) {
    __shared__ float ts[16][68];
    int bc = blockIdx.x;
    int c  = bc & 255;
    int t  = threadIdx.x;
    float a = g_a[c], b2 = g_b2[c];
    int kk = t >> 4, n4 = (t & 15) << 2;
    int nn = t >> 2, kg = (t & 3) << 2;
    for (int n0 = 0; n0 < NNDIM; n0 += 64) {
        float4 v = *(const float4*)&g_t[((size_t)bc * KDIM + kk) * NNDIM + n0 + n4];
        *(float4*)&ts[kk][n4] = v;
        __syncthreads();
        float4 tv = make_float4(ts[kg][nn], ts[kg + 1][nn], ts[kg + 2][nn], ts[kg + 3][nn]);
        tv.x = fmaxf(tv.x * a + b2, 0.0f);
        tv.y = fmaxf(tv.y * a + b2, 0.0f);
        tv.z = fmaxf(tv.z * a + b2, 0.0f);
        tv.w = fmaxf(tv.w * a + b2, 0.0f);
        size_t idx = ((size_t)bc * NNDIM + n0 + nn) * KDIM + kg;
        float4 xv = *(const float4*)&x[idx];
        tv.x += xv.x; tv.y += xv.y; tv.z += xv.z; tv.w += xv.w;
        *(float4*)&out[idx] = tv;
        __syncthreads();
    }
}

// ---------------- launch ----------------
extern "C" void kernel_launch(void* const* d_in, const int* in_sizes, int n_in,
                              void* d_out, int out_size) {
    const float* x     = (const float*)d_in[0];
    const float* q_w   = (const float*)d_in[1];
    const float* k_w   = (const float*)d_in[2];
    const float* v_w   = (const float*)d_in[3];
    const float* v_b   = (const float*)d_in[4];
    const float* t_w   = (const float*)d_in[5];
    const float* t_b   = (const float*)d_in[6];
    const float* gamma = (const float*)d_in[7];
    const float* beta  = (const float*)d_in[8];
    float* out = (float*)d_out;

    k_concat<<<384, 256>>>(q_w, k_w, v_w);
    k_transpose_x<<<BB * CC, 256>>>(x);
    k_mma<1><<<dim3(8, 3, BB * KDIM), 256>>>(nullptr, v_b);     // q/k/v projection
    k_split<<<BB * KDIM * 32, 256>>>();                         // q/k -> packed fp16 hi/lo
    k_energy_v3<<<dim3(32, BB * KDIM), 512>>>();                // energy + softmax -> S^T fp32
    k_renorm_cvt<<<8192, 256>>>();                              // renorm fp32 -> fp16 g_Sh
    k_mma<0><<<dim3(8, 2, BB * KDIM), 256>>>(nullptr, nullptr); // x_r + (x - x_r)
    k_mma<2><<<dim3(8, 2, BB * KDIM), 256>>>(t_w, t_b);         // t projection
    k_stats<<<CC, 256>>>(gamma, beta);
    k_final<<<BB * CC, 256>>>(x, out);
}

// round 14
// speedup vs baseline: 1.4328x; 1.4328x over previous
#include <cuda_runtime.h>
#include <cuda_fp16.h>
#include <cstdint>
#include <cstddef>

#define BB 8
#define CC 256
#define NNDIM 1024
#define KDIM 16
#define CQ 64

// ---------------- scratch (device globals; no allocation allowed) ----------------
__device__ float g_wcat[384 * 256];                              // concat q/k/v weights
__device__ float g_xT[(size_t)BB * KDIM * CC * NNDIM];           // [b][k][c][n]
__device__ float g_xq2[(size_t)BB * KDIM * (CQ/2) * NNDIM * 2];  // [z][cq/2][n] (hi2,lo2) fp16x2
__device__ float g_xk2[(size_t)BB * KDIM * (CQ/2) * NNDIM * 2];  // [z][cq/2][n]
__device__ float g_xv[(size_t)BB * KDIM * CC * NNDIM];           // [b][k][c][n]
__device__ float g_S [(size_t)BB * KDIM * NNDIM * NNDIM];        // S^T pre-renorm fp32 [z][m][n]
__device__ __half g_Sh[(size_t)BB * KDIM * NNDIM * NNDIM];       // S^T renormalized fp16 [z][m][n]
__device__ float g_d [(size_t)BB * KDIM * CC * NNDIM];           // x - x_r
__device__ float g_t [(size_t)BB * CC * KDIM * NNDIM];           // t proj [b][c][k][n]
__device__ float g_a [CC];
__device__ float g_b2[CC];

__device__ __forceinline__ uint32_t f2tf32(float f) {
    uint32_t u;
    asm("cvt.rna.tf32.f32 %0, %1;" : "=r"(u) : "f"(f));
    return u;
}

__device__ __forceinline__ void mma_tf32(float c[4], const uint32_t a[4], const uint32_t b[2]) {
    asm volatile("mma.sync.aligned.m16n8k8.row.col.f32.tf32.tf32.f32 "
                 "{%0,%1,%2,%3}, {%4,%5,%6,%7}, {%8,%9}, {%0,%1,%2,%3};"
                 : "+f"(c[0]), "+f"(c[1]), "+f"(c[2]), "+f"(c[3])
                 : "r"(a[0]), "r"(a[1]), "r"(a[2]), "r"(a[3]), "r"(b[0]), "r"(b[1]));
}

__device__ __forceinline__ void mma_f16(float c[4], const uint32_t a[4], const uint32_t b[2]) {
    asm volatile("mma.sync.aligned.m16n8k16.row.col.f32.f16.f16.f32 "
                 "{%0,%1,%2,%3}, {%4,%5,%6,%7}, {%8,%9}, {%0,%1,%2,%3};"
                 : "+f"(c[0]), "+f"(c[1]), "+f"(c[2]), "+f"(c[3])
                 : "r"(a[0]), "r"(a[1]), "r"(a[2]), "r"(a[3]), "r"(b[0]), "r"(b[1]));
}

// pack two floats into (hi fp16x2, lo fp16x2) residual-split float2
__device__ __forceinline__ float2 pack_hilo(float a, float b) {
    __half ha = __float2half_rn(a), hb = __float2half_rn(b);
    float la = a - __half2float(ha), lb = b - __half2float(hb);
    __half2 h2 = __halves2half2(ha, hb);
    __half2 l2 = __halves2half2(__float2half_rn(la), __float2half_rn(lb));
    float2 o;
    o.x = __uint_as_float(*(uint32_t*)&h2);
    o.y = __uint_as_float(*(uint32_t*)&l2);
    return o;
}

// ---------------- kernel 0: concat weights ----------------
__global__ void k_concat(const float* __restrict__ q_w, const float* __restrict__ k_w,
                         const float* __restrict__ v_w) {
    int i = blockIdx.x * 256 + threadIdx.x;
    if (i >= 384 * 256) return;
    int o = i >> 8;
    float v;
    if (o < 64)        v = q_w[i];
    else if (o < 128)  v = k_w[i - 64 * 256];
    else               v = v_w[i - 128 * 256];
    g_wcat[i] = v;
}

// ---------------- kernel 1: transpose x [b,c,n,k] -> xT [b,k,c,n] ----------------
__global__ void k_transpose_x(const float* __restrict__ x) {
    __shared__ float ts[16][68];
    int bc = blockIdx.x;
    int b = bc >> 8, c = bc & 255;
    int t = threadIdx.x;
    int nn = t >> 2, kg = (t & 3) << 2;
    int kk = t >> 4, n4 = (t & 15) << 2;
    for (int n0 = 0; n0 < NNDIM; n0 += 64) {
        float4 v = *(const float4*)&x[(((size_t)bc * NNDIM) + n0 + nn) * KDIM + kg];
        ts[kg + 0][nn] = v.x; ts[kg + 1][nn] = v.y; ts[kg + 2][nn] = v.z; ts[kg + 3][nn] = v.w;
        __syncthreads();
        float4 o = make_float4(ts[kk][n4], ts[kk][n4 + 1], ts[kk][n4 + 2], ts[kk][n4 + 3]);
        *(float4*)&g_xT[(((size_t)(b * KDIM + kk) * CC + c) * NNDIM) + n0 + n4] = o;
        __syncthreads();
    }
}

// ---------------- unified tf32 mma.sync tile GEMM (proj / xr / tproj) ----------------
// MODE 0: xr   : A=g_xv[z],  B=g_Sh^T[z] fp16 (K-major direct). K=1024. epi: d = xT - acc
// MODE 1: proj : A=g_wcat,   B=g_xT[z] (transpose-load). K=256. epi: q/k packed hi/lo, v(+bias)
// MODE 2: tproj: A=t_w,      B=g_d[z]  (transpose-load). K=256. epi: +bias -> g_t
template<int MODE>
__global__ __launch_bounds__(256) void k_mma(const float* __restrict__ A_ext,
                                             const float* __restrict__ bias) {
    __shared__ uint32_t As[128][36];
    __shared__ uint32_t Bs[128][36];

    const int t = threadIdx.x;
    const int wid = t >> 5, lane = t & 31;
    const int gr = lane >> 2, tg = lane & 3;
    const int wm = (wid >> 2) * 64, wn = (wid & 3) * 32;
    const int z  = blockIdx.z;
    const int n0 = blockIdx.x << 7;
    const int m0 = blockIdx.y << 7;
    const int KTOT = (MODE == 0) ? 1024 : 256;
    const int NC = KTOT / 32;
    const unsigned FULL = 0xffffffffu;

    const float* Ap;
    const float* Bp = nullptr;
    const __half* Bh = nullptr;
    if (MODE == 0) {
        Ap = g_xv + ((size_t)z * CC + m0) * NNDIM;
        Bh = g_Sh + (size_t)z * NNDIM * NNDIM + (size_t)n0 * NNDIM;
    } else if (MODE == 1) {
        Ap = g_wcat + (size_t)m0 * 256;
        Bp = g_xT + (size_t)z * CC * NNDIM + n0;
    } else {
        Ap = A_ext + (size_t)m0 * 256;
        Bp = g_d + (size_t)z * CC * NNDIM + n0;
    }
    const int lda = (MODE == 0) ? NNDIM : 256;

    float ra[16], rb[16];
    const int arow = t >> 1, ah = (t & 1) << 4;
    const int bc_ = t >> 3, bn4 = (t & 7) << 4;

    auto loadA = [&](int k0) {
#pragma unroll
        for (int j = 0; j < 4; j++) {
            float4 v = *(const float4*)&Ap[(size_t)arow * lda + k0 + ah + j * 4];
            ra[j * 4 + 0] = v.x; ra[j * 4 + 1] = v.y; ra[j * 4 + 2] = v.z; ra[j * 4 + 3] = v.w;
        }
    };
    auto loadB = [&](int k0) {
        if (MODE == 0) {
            // 16 halves = 32 bytes = TWO uint4 loads
            uint4 u0 = *(const uint4*)&Bh[(size_t)arow * NNDIM + k0 + ah];
            uint4 u1 = *(const uint4*)&Bh[(size_t)arow * NNDIM + k0 + ah + 8];
            const __half2* h0 = (const __half2*)&u0;
            const __half2* h1 = (const __half2*)&u1;
#pragma unroll
            for (int j = 0; j < 4; j++) {
                float2 f = __half22float2(h0[j]);
                rb[2 * j] = f.x; rb[2 * j + 1] = f.y;
            }
#pragma unroll
            for (int j = 0; j < 4; j++) {
                float2 f = __half22float2(h1[j]);
                rb[8 + 2 * j] = f.x; rb[8 + 2 * j + 1] = f.y;
            }
        } else {
#pragma unroll
            for (int j = 0; j < 4; j++) {
                float4 v = *(const float4*)&Bp[(size_t)(k0 + bc_) * NNDIM + bn4 + j * 4];
                rb[j * 4 + 0] = v.x; rb[j * 4 + 1] = v.y; rb[j * 4 + 2] = v.z; rb[j * 4 + 3] = v.w;
            }
        }
    };
    auto storeAB = [&]() {
#pragma unroll
        for (int j = 0; j < 16; j++) As[arow][ah + j] = f2tf32(ra[j]);
        if (MODE == 0) {
#pragma unroll
            for (int j = 0; j < 16; j++) Bs[arow][ah + j] = f2tf32(rb[j]);
        } else {
#pragma unroll
            for (int j = 0; j < 16; j++) Bs[bn4 + j][bc_] = f2tf32(rb[j]);
        }
    };

    float acc[4][4][4] = {};
    loadA(0); loadB(0);
    for (int c = 0; c < NC; c++) {
        __syncthreads();
        storeAB();
        __syncthreads();
        if (c + 1 < NC) { loadA((c + 1) * 32); loadB((c + 1) * 32); }
#pragma unroll
        for (int ks = 0; ks < 4; ks++) {
            int k0 = ks * 8;
            uint32_t af[4][4], bf[4][2];
#pragma unroll
            for (int mt = 0; mt < 4; mt++) {
                int r = wm + mt * 16 + gr;
                af[mt][0] = As[r][k0 + tg];
                af[mt][1] = As[r + 8][k0 + tg];
                af[mt][2] = As[r][k0 + tg + 4];
                af[mt][3] = As[r + 8][k0 + tg + 4];
            }
#pragma unroll
            for (int nt = 0; nt < 4; nt++) {
                int r = wn + nt * 8 + gr;
                bf[nt][0] = Bs[r][k0 + tg];
                bf[nt][1] = Bs[r][k0 + tg + 4];
            }
#pragma unroll
            for (int mt = 0; mt < 4; mt++)
#pragma unroll
                for (int nt = 0; nt < 4; nt++)
                    mma_tf32(acc[mt][nt], af[mt], bf[nt]);
        }
    }

#pragma unroll
    for (int mt = 0; mt < 4; mt++) {
#pragma unroll
        for (int nt = 0; nt < 4; nt++) {
#pragma unroll
            for (int h = 0; h < 2; h++) {
                int row = m0 + wm + mt * 16 + gr + h * 8;
                int col = n0 + wn + nt * 8 + 2 * tg;
                float v0 = acc[mt][nt][h * 2 + 0];
                float v1 = acc[mt][nt][h * 2 + 1];
                if (MODE == 0) {
                    size_t idx = ((size_t)z * CC + row) * NNDIM + col;
                    float2 xv = *(const float2*)&g_xT[idx];
                    *(float2*)&g_d[idx] = make_float2(xv.x - v0, xv.y - v1);
                } else if (MODE == 1) {
                    if (row < 128) {
                        // channel-pair partner (row^1) lives at lane^4 (gr^1)
                        float p0 = __shfl_xor_sync(FULL, v0, 4);
                        float p1 = __shfl_xor_sync(FULL, v1, 4);
                        if (!(gr & 1)) {
                            bool isq = row < 64;
                            int c2 = (row & 63) >> 1;
                            float2* dst = (float2*)(isq ? g_xq2 : g_xk2)
                                        + ((size_t)z * 32 + c2) * NNDIM + col;
                            dst[0] = pack_hilo(v0, p0);
                            dst[1] = pack_hilo(v1, p1);
                        }
                    } else {
                        float bb = bias[row - 128];
                        *(float2*)&g_xv[((size_t)z * CC + row - 128) * NNDIM + col] =
                            make_float2(v0 + bb, v1 + bb);
                    }
                } else {
                    float bb = bias[row];
                    int b = z >> 4, kb = z & 15;
                    *(float2*)&g_t[(((size_t)(b * CC + row)) * KDIM + kb) * NNDIM + col] =
                        make_float2(v0 + bb, v1 + bb);
                }
            }
        }
    }
}

// ---------------- kernel 3: energy (split-fp16 mma) + softmax, writes S^T fp32 [z][m][n] ----------------
__global__ __launch_bounds__(512) void k_energy_v3() {
    __shared__ float redmax[32][9];
    __shared__ float redsum[32][9];
    int z  = blockIdx.y;
    int n0 = blockIdx.x << 5;
    int t  = threadIdx.x;
    int wid = t >> 5, lane = t & 31;
    int gr = lane >> 2, tg = lane & 3;
    int wn2 = wid >> 3;
    int wm8 = wid & 7;
    int r0 = wn2 * 16 + gr;
    int nrow = n0 + r0;
    int mb = wm8 << 7;
    const float2* q2 = (const float2*)g_xq2 + (size_t)z * 32 * NNDIM;
    const float2* k2 = (const float2*)g_xk2 + (size_t)z * 32 * NNDIM;

    float acc[16][4] = {};
#pragma unroll
    for (int ks = 0; ks < 4; ks++) {
        int p0 = ks << 3;
        float2 A0 = q2[(size_t)(p0 + tg) * NNDIM + nrow];
        float2 A1 = q2[(size_t)(p0 + tg) * NNDIM + nrow + 8];
        float2 A2 = q2[(size_t)(p0 + tg + 4) * NNDIM + nrow];
        float2 A3 = q2[(size_t)(p0 + tg + 4) * NNDIM + nrow + 8];
        uint32_t ah[4] = {__float_as_uint(A0.x), __float_as_uint(A1.x),
                          __float_as_uint(A2.x), __float_as_uint(A3.x)};
        uint32_t al[4] = {__float_as_uint(A0.y), __float_as_uint(A1.y),
                          __float_as_uint(A2.y), __float_as_uint(A3.y)};
#pragma unroll
        for (int nf = 0; nf < 16; nf++) {
            int m = mb + nf * 8 + gr;
            float2 B0 = k2[(size_t)(p0 + tg) * NNDIM + m];
            float2 B1 = k2[(size_t)(p0 + tg + 4) * NNDIM + m];
            uint32_t bh[2] = {__float_as_uint(B0.x), __float_as_uint(B1.x)};
            uint32_t bl[2] = {__float_as_uint(B0.y), __float_as_uint(B1.y)};
            mma_f16(acc[nf], ah, bh);
            mma_f16(acc[nf], ah, bl);
            mma_f16(acc[nf], al, bh);
        }
    }
    const unsigned FULL = 0xffffffffu;
    float m0 = -1e30f, m1 = -1e30f;
#pragma unroll
    for (int nf = 0; nf < 16; nf++) {
        m0 = fmaxf(m0, fmaxf(acc[nf][0], acc[nf][1]));
        m1 = fmaxf(m1, fmaxf(acc[nf][2], acc[nf][3]));
    }
    m0 = fmaxf(m0, __shfl_xor_sync(FULL, m0, 1));
    m0 = fmaxf(m0, __shfl_xor_sync(FULL, m0, 2));
    m1 = fmaxf(m1, __shfl_xor_sync(FULL, m1, 1));
    m1 = fmaxf(m1, __shfl_xor_sync(FULL, m1, 2));
    if (tg == 0) { redmax[r0][wm8] = m0; redmax[r0 + 8][wm8] = m1; }
    __syncthreads();
    float mx0 = -1e30f, mx1 = -1e30f;
#pragma unroll
    for (int j = 0; j < 8; j++) {
        mx0 = fmaxf(mx0, redmax[r0][j]);
        mx1 = fmaxf(mx1, redmax[r0 + 8][j]);
    }
    float s0 = 0.0f, s1 = 0.0f;
#pragma unroll
    for (int nf = 0; nf < 16; nf++) {
        acc[nf][0] = __expf(acc[nf][0] - mx0);
        acc[nf][1] = __expf(acc[nf][1] - mx0);
        acc[nf][2] = __expf(acc[nf][2] - mx1);
        acc[nf][3] = __expf(acc[nf][3] - mx1);
        s0 += acc[nf][0] + acc[nf][1];
        s1 += acc[nf][2] + acc[nf][3];
    }
    s0 += __shfl_xor_sync(FULL, s0, 1);
    s0 += __shfl_xor_sync(FULL, s0, 2);
    s1 += __shfl_xor_sync(FULL, s1, 1);
    s1 += __shfl_xor_sync(FULL, s1, 2);
    if (tg == 0) { redsum[r0][wm8] = s0; redsum[r0 + 8][wm8] = s1; }
    __syncthreads();
    float sum0 = 0.0f, sum1 = 0.0f;
#pragma unroll
    for (int j = 0; j < 8; j++) {
        sum0 += redsum[r0][j];
        sum1 += redsum[r0 + 8][j];
    }
    float inv0 = 1.0f / sum0, inv1 = 1.0f / sum1;
    float* ST = g_S + (size_t)z * NNDIM * NNDIM;
#pragma unroll
    for (int nf = 0; nf < 16; nf++) {
        int m = mb + nf * 8 + 2 * tg;
        float* c0 = ST + (size_t)m * NNDIM + nrow;
        float* c1 = c0 + NNDIM;
        c0[0] = acc[nf][0] * inv0;
        c1[0] = acc[nf][1] * inv0;
        c0[8] = acc[nf][2] * inv1;
        c1[8] = acc[nf][3] * inv1;
    }
}

// ---------------- kernel 4: cross-K renorm: fp32 in, renormalized fp16 out ----------------
__global__ void k_renorm_cvt() {
    size_t p = (size_t)blockIdx.x * 256 + threadIdx.x;   // < 8 * 262144
    int b = (int)(p >> 18);
    size_t off = (size_t)(p & 262143) << 2;              // 4 floats per thread
    const size_t ks = (size_t)NNDIM * NNDIM;
    size_t base = (size_t)b * KDIM * ks + off;
    float4 v[16];
    float4 s = make_float4(1e-9f, 1e-9f, 1e-9f, 1e-9f);
#pragma unroll
    for (int k = 0; k < 16; k++) {
        v[k] = *(const float4*)&g_S[base + (size_t)k * ks];
        s.x += v[k].x; s.y += v[k].y; s.z += v[k].z; s.w += v[k].w;
    }
    float4 inv = make_float4(1.0f / s.x, 1.0f / s.y, 1.0f / s.z, 1.0f / s.w);
#pragma unroll
    for (int k = 0; k < 16; k++) {
        __half2 h01 = __floats2half2_rn(v[k].x * inv.x, v[k].y * inv.y);
        __half2 h23 = __floats2half2_rn(v[k].z * inv.z, v[k].w * inv.w);
        uint2 o;
        o.x = *(uint32_t*)&h01;
        o.y = *(uint32_t*)&h23;
        *(uint2*)&g_Sh[base + (size_t)k * ks] = o;
    }
}

// ---------------- kernel 7: BN stats per channel ----------------
__global__ void k_stats(const float* __restrict__ gamma, const float* __restrict__ beta) {
    int c = blockIdx.x;
    int t = threadIdx.x;
    float s = 0.0f, sq = 0.0f;
    for (int b = 0; b < BB; b++) {
        const float* base = g_t + ((size_t)(b * CC + c)) * KDIM * NNDIM;
        for (int fl = t; fl < 4096; fl += 256) {
            float4 v = *(const float4*)&base[fl * 4];
            s  += v.x + v.y + v.z + v.w;
            sq += v.x * v.x + v.y * v.y + v.z * v.z + v.w * v.w;
        }
    }
    __shared__ float ss[256], sqq[256];
    ss[t] = s; sqq[t] = sq;
    __syncthreads();
    for (int o = 128; o > 0; o >>= 1) {
        if (t < o) { ss[t] += ss[t + o]; sqq[t] += sqq[t + o]; }
        __syncthreads();
    }
    if (t == 0) {
        const float cnt = 131072.0f;
        float mean = ss[0] / cnt;
        float var  = sqq[0] / cnt - mean * mean;
        float rstd = rsqrtf(var + 1e-5f);
        float a = rstd * gamma[c];
        g_a[c]  = a;
        g_b2[c] = beta[c] - mean * a;
    }
}

// ---------------- kernel 8: out = x + relu(t*a + b2), transpose [k][n]->[n][k] ----------------
__global__ void k_final(const float* __restrict__ x, float* __restrict__ out) {
    __shared__ float ts[16][68];
    int bc = blockIdx.x;
    int c  = bc & 255;
    int t  = threadIdx.x;
    float a = g_a[c], b2 = g_b2[c];
    int kk = t >> 4, n4 = (t & 15) << 2;
    int nn = t >> 2, kg = (t & 3) << 2;
    for (int n0 = 0; n0 < NNDIM; n0 += 64) {
        float4 v = *(const float4*)&g_t[((size_t)bc * KDIM + kk) * NNDIM + n0 + n4];
        *(float4*)&ts[kk][n4] = v;
        __syncthreads();
        float4 tv = make_float4(ts[kg][nn], ts[kg + 1][nn], ts[kg + 2][nn], ts[kg + 3][nn]);
        tv.x = fmaxf(tv.x * a + b2, 0.0f);
        tv.y = fmaxf(tv.y * a + b2, 0.0f);
        tv.z = fmaxf(tv.z * a + b2, 0.0f);
        tv.w = fmaxf(tv.w * a + b2, 0.0f);
        size_t idx = ((size_t)bc * NNDIM + n0 + nn) * KDIM + kg;
        float4 xv = *(const float4*)&x[idx];
        tv.x += xv.x; tv.y += xv.y; tv.z += xv.z; tv.w += xv.w;
        *(float4*)&out[idx] = tv;
        __syncthreads();
    }
}

// ---------------- launch ----------------
extern "C" void kernel_launch(void* const* d_in, const int* in_sizes, int n_in,
                              void* d_out, int out_size) {
    const float* x     = (const float*)d_in[0];
    const float* q_w   = (const float*)d_in[1];
    const float* k_w   = (const float*)d_in[2];
    const float* v_w   = (const float*)d_in[3];
    const float* v_b   = (const float*)d_in[4];
    const float* t_w   = (const float*)d_in[5];
    const float* t_b   = (const float*)d_in[6];
    const float* gamma = (const float*)d_in[7];
    const float* beta  = (const float*)d_in[8];
    float* out = (float*)d_out;

    k_concat<<<384, 256>>>(q_w, k_w, v_w);
    k_transpose_x<<<BB * CC, 256>>>(x);
    k_mma<1><<<dim3(8, 3, BB * KDIM), 256>>>(nullptr, v_b);     // q/k/v proj (+fused hi/lo pack)
    k_energy_v3<<<dim3(32, BB * KDIM), 512>>>();                // energy + softmax -> S^T fp32
    k_renorm_cvt<<<8192, 256>>>();                              // renorm fp32 -> fp16 g_Sh
    k_mma<0><<<dim3(8, 2, BB * KDIM), 256>>>(nullptr, nullptr); // x_r + (x - x_r)
    k_mma<2><<<dim3(8, 2, BB * KDIM), 256>>>(t_w, t_b);         // t projection
    k_stats<<<CC, 256>>>(gamma, beta);
    k_final<<<BB * CC, 256>>>(x, out);
}

// round 16
// speedup vs baseline: 1.4377x; 1.0034x over previous
#include <cuda_runtime.h>
#include <cuda_fp16.h>
#include <cstdint>
#include <cstddef>

#define BB 8
#define CC 256
#define NNDIM 1024
#define KDIM 16
#define CQ 64

// ---------------- scratch (device globals; no allocation allowed) ----------------
__device__ float g_wcat[384 * 256];                              // concat q/k/v weights
__device__ float g_xT[(size_t)BB * KDIM * CC * NNDIM];           // [b][k][c][n]
__device__ float g_xq2[(size_t)BB * KDIM * (CQ/2) * NNDIM * 2];  // [z][cq/2][n] (hi2,lo2) fp16x2
__device__ float g_xk2[(size_t)BB * KDIM * (CQ/2) * NNDIM * 2];  // [z][cq/2][n]
__device__ float g_xv[(size_t)BB * KDIM * CC * NNDIM];           // [b][k][c][n]
__device__ float g_S [(size_t)BB * KDIM * NNDIM * NNDIM];        // S^T pre-renorm fp32 [z][m][n]
__device__ __half g_Sh[(size_t)BB * KDIM * NNDIM * NNDIM];       // S^T renormalized fp16 [z][m][n]
__device__ float g_d [(size_t)BB * KDIM * CC * NNDIM];           // x - x_r
__device__ float g_t [(size_t)BB * CC * KDIM * NNDIM];           // t proj [b][c][k][n]
__device__ float g_a [CC];
__device__ float g_b2[CC];

__device__ __forceinline__ uint32_t f2tf32(float f) {
    uint32_t u;
    asm("cvt.rna.tf32.f32 %0, %1;" : "=r"(u) : "f"(f));
    return u;
}

__device__ __forceinline__ void mma_tf32(float c[4], const uint32_t a[4], const uint32_t b[2]) {
    asm volatile("mma.sync.aligned.m16n8k8.row.col.f32.tf32.tf32.f32 "
                 "{%0,%1,%2,%3}, {%4,%5,%6,%7}, {%8,%9}, {%0,%1,%2,%3};"
                 : "+f"(c[0]), "+f"(c[1]), "+f"(c[2]), "+f"(c[3])
                 : "r"(a[0]), "r"(a[1]), "r"(a[2]), "r"(a[3]), "r"(b[0]), "r"(b[1]));
}

__device__ __forceinline__ void mma_f16(float c[4], const uint32_t a[4], const uint32_t b[2]) {
    asm volatile("mma.sync.aligned.m16n8k16.row.col.f32.f16.f16.f32 "
                 "{%0,%1,%2,%3}, {%4,%5,%6,%7}, {%8,%9}, {%0,%1,%2,%3};"
                 : "+f"(c[0]), "+f"(c[1]), "+f"(c[2]), "+f"(c[3])
                 : "r"(a[0]), "r"(a[1]), "r"(a[2]), "r"(a[3]), "r"(b[0]), "r"(b[1]));
}

// pack two floats into (hi fp16x2, lo fp16x2) residual-split float2
__device__ __forceinline__ float2 pack_hilo(float a, float b) {
    __half ha = __float2half_rn(a), hb = __float2half_rn(b);
    float la = a - __half2float(ha), lb = b - __half2float(hb);
    __half2 h2 = __halves2half2(ha, hb);
    __half2 l2 = __halves2half2(__float2half_rn(la), __float2half_rn(lb));
    float2 o;
    o.x = __uint_as_float(*(uint32_t*)&h2);
    o.y = __uint_as_float(*(uint32_t*)&l2);
    return o;
}

// ---------------- kernel 0: concat weights ----------------
__global__ void k_concat(const float* __restrict__ q_w, const float* __restrict__ k_w,
                         const float* __restrict__ v_w) {
    int i = blockIdx.x * 256 + threadIdx.x;
    if (i >= 384 * 256) return;
    int o = i >> 8;
    float v;
    if (o < 64)        v = q_w[i];
    else if (o < 128)  v = k_w[i - 64 * 256];
    else               v = v_w[i - 128 * 256];
    g_wcat[i] = v;
}

// ---------------- kernel 1: transpose x [b,c,n,k] -> xT [b,k,c,n] ----------------
__global__ void k_transpose_x(const float* __restrict__ x) {
    __shared__ float ts[16][68];
    int bc = blockIdx.x;
    int b = bc >> 8, c = bc & 255;
    int t = threadIdx.x;
    int nn = t >> 2, kg = (t & 3) << 2;
    int kk = t >> 4, n4 = (t & 15) << 2;
    for (int n0 = 0; n0 < NNDIM; n0 += 64) {
        float4 v = *(const float4*)&x[(((size_t)bc * NNDIM) + n0 + nn) * KDIM + kg];
        ts[kg + 0][nn] = v.x; ts[kg + 1][nn] = v.y; ts[kg + 2][nn] = v.z; ts[kg + 3][nn] = v.w;
        __syncthreads();
        float4 o = make_float4(ts[kk][n4], ts[kk][n4 + 1], ts[kk][n4 + 2], ts[kk][n4 + 3]);
        *(float4*)&g_xT[(((size_t)(b * KDIM + kk) * CC + c) * NNDIM) + n0 + n4] = o;
        __syncthreads();
    }
}

// ---------------- unified tf32 mma.sync tile GEMM (proj / xr / tproj) ----------------
// MODE 0: xr   : A=g_xv[z],  B=g_Sh^T[z] fp16 (K-major direct). K=1024. epi: d = xT - acc
// MODE 1: proj : A=g_wcat,   B=g_xT[z] (transpose-load). K=256. epi: q/k packed hi/lo, v(+bias)
// MODE 2: tproj: A=t_w,      B=g_d[z]  (transpose-load). K=256. epi: +bias -> g_t
template<int MODE>
__global__ __launch_bounds__(256) void k_mma(const float* __restrict__ A_ext,
                                             const float* __restrict__ bias) {
    __shared__ uint32_t As[128][36];
    __shared__ uint32_t Bs[128][36];

    const int t = threadIdx.x;
    const int wid = t >> 5, lane = t & 31;
    const int gr = lane >> 2, tg = lane & 3;
    const int wm = (wid >> 2) * 64, wn = (wid & 3) * 32;
    const int z  = blockIdx.z;
    const int n0 = blockIdx.x << 7;
    const int m0 = blockIdx.y << 7;
    const int KTOT = (MODE == 0) ? 1024 : 256;
    const int NC = KTOT / 32;
    const unsigned FULL = 0xffffffffu;

    const float* Ap;
    const float* Bp = nullptr;
    const __half* Bh = nullptr;
    if (MODE == 0) {
        Ap = g_xv + ((size_t)z * CC + m0) * NNDIM;
        Bh = g_Sh + (size_t)z * NNDIM * NNDIM + (size_t)n0 * NNDIM;
    } else if (MODE == 1) {
        Ap = g_wcat + (size_t)m0 * 256;
        Bp = g_xT + (size_t)z * CC * NNDIM + n0;
    } else {
        Ap = A_ext + (size_t)m0 * 256;
        Bp = g_d + (size_t)z * CC * NNDIM + n0;
    }
    const int lda = (MODE == 0) ? NNDIM : 256;

    float ra[16], rb[16];
    const int arow = t >> 1, ah = (t & 1) << 4;
    const int bc_ = t >> 3, bn4 = (t & 7) << 4;

    auto loadA = [&](int k0) {
#pragma unroll
        for (int j = 0; j < 4; j++) {
            float4 v = *(const float4*)&Ap[(size_t)arow * lda + k0 + ah + j * 4];
            ra[j * 4 + 0] = v.x; ra[j * 4 + 1] = v.y; ra[j * 4 + 2] = v.z; ra[j * 4 + 3] = v.w;
        }
    };
    auto loadB = [&](int k0) {
        if (MODE == 0) {
            uint4 u0 = *(const uint4*)&Bh[(size_t)arow * NNDIM + k0 + ah];
            uint4 u1 = *(const uint4*)&Bh[(size_t)arow * NNDIM + k0 + ah + 8];
            const __half2* h0 = (const __half2*)&u0;
            const __half2* h1 = (const __half2*)&u1;
#pragma unroll
            for (int j = 0; j < 4; j++) {
                float2 f = __half22float2(h0[j]);
                rb[2 * j] = f.x; rb[2 * j + 1] = f.y;
            }
#pragma unroll
            for (int j = 0; j < 4; j++) {
                float2 f = __half22float2(h1[j]);
                rb[8 + 2 * j] = f.x; rb[8 + 2 * j + 1] = f.y;
            }
        } else {
#pragma unroll
            for (int j = 0; j < 4; j++) {
                float4 v = *(const float4*)&Bp[(size_t)(k0 + bc_) * NNDIM + bn4 + j * 4];
                rb[j * 4 + 0] = v.x; rb[j * 4 + 1] = v.y; rb[j * 4 + 2] = v.z; rb[j * 4 + 3] = v.w;
            }
        }
    };
    auto storeAB = [&]() {
#pragma unroll
        for (int j = 0; j < 16; j++) As[arow][ah + j] = f2tf32(ra[j]);
        if (MODE == 0) {
#pragma unroll
            for (int j = 0; j < 16; j++) Bs[arow][ah + j] = f2tf32(rb[j]);
        } else {
#pragma unroll
            for (int j = 0; j < 16; j++) Bs[bn4 + j][bc_] = f2tf32(rb[j]);
        }
    };

    float acc[4][4][4] = {};
    loadA(0); loadB(0);
    for (int c = 0; c < NC; c++) {
        __syncthreads();
        storeAB();
        __syncthreads();
        if (c + 1 < NC) { loadA((c + 1) * 32); loadB((c + 1) * 32); }
#pragma unroll
        for (int ks = 0; ks < 4; ks++) {
            int k0 = ks * 8;
            uint32_t af[4][4], bf[4][2];
#pragma unroll
            for (int mt = 0; mt < 4; mt++) {
                int r = wm + mt * 16 + gr;
                af[mt][0] = As[r][k0 + tg];
                af[mt][1] = As[r + 8][k0 + tg];
                af[mt][2] = As[r][k0 + tg + 4];
                af[mt][3] = As[r + 8][k0 + tg + 4];
            }
#pragma unroll
            for (int nt = 0; nt < 4; nt++) {
                int r = wn + nt * 8 + gr;
                bf[nt][0] = Bs[r][k0 + tg];
                bf[nt][1] = Bs[r][k0 + tg + 4];
            }
#pragma unroll
            for (int mt = 0; mt < 4; mt++)
#pragma unroll
                for (int nt = 0; nt < 4; nt++)
                    mma_tf32(acc[mt][nt], af[mt], bf[nt]);
        }
    }

#pragma unroll
    for (int mt = 0; mt < 4; mt++) {
#pragma unroll
        for (int nt = 0; nt < 4; nt++) {
#pragma unroll
            for (int h = 0; h < 2; h++) {
                int row = m0 + wm + mt * 16 + gr + h * 8;
                int col = n0 + wn + nt * 8 + 2 * tg;
                float v0 = acc[mt][nt][h * 2 + 0];
                float v1 = acc[mt][nt][h * 2 + 1];
                if (MODE == 0) {
                    size_t idx = ((size_t)z * CC + row) * NNDIM + col;
                    float2 xv = *(const float2*)&g_xT[idx];
                    *(float2*)&g_d[idx] = make_float2(xv.x - v0, xv.y - v1);
                } else if (MODE == 1) {
                    if (row < 128) {
                        float p0 = __shfl_xor_sync(FULL, v0, 4);
                        float p1 = __shfl_xor_sync(FULL, v1, 4);
                        if (!(gr & 1)) {
                            bool isq = row < 64;
                            int c2 = (row & 63) >> 1;
                            float2* dst = (float2*)(isq ? g_xq2 : g_xk2)
                                        + ((size_t)z * 32 + c2) * NNDIM + col;
                            dst[0] = pack_hilo(v0, p0);
                            dst[1] = pack_hilo(v1, p1);
                        }
                    } else {
                        float bb = bias[row - 128];
                        *(float2*)&g_xv[((size_t)z * CC + row - 128) * NNDIM + col] =
                            make_float2(v0 + bb, v1 + bb);
                    }
                } else {
                    float bb = bias[row];
                    int b = z >> 4, kb = z & 15;
                    *(float2*)&g_t[(((size_t)(b * CC + row)) * KDIM + kb) * NNDIM + col] =
                        make_float2(v0 + bb, v1 + bb);
                }
            }
        }
    }
}

// ---------------- kernel 3: energy (split-fp16 mma) + softmax, writes S^T fp32 [z][m][n] ----------------
// Batched B loads: per ks-slice, 2 halves of 8 nf; each half issues its 16 loads before
// any MMA -> MLP ~16 to cover L2 latency (1 block/SM, no occupancy to hide it otherwise).
__global__ __launch_bounds__(512) void k_energy_v4() {
    __shared__ float redmax[32][9];
    __shared__ float redsum[32][9];
    int z  = blockIdx.y;
    int n0 = blockIdx.x << 5;
    int t  = threadIdx.x;
    int wid = t >> 5, lane = t & 31;
    int gr = lane >> 2, tg = lane & 3;
    int wn2 = wid >> 3;
    int wm8 = wid & 7;
    int r0 = wn2 * 16 + gr;
    int nrow = n0 + r0;
    int mb = wm8 << 7;
    const float2* q2 = (const float2*)g_xq2 + (size_t)z * 32 * NNDIM;
    const float2* k2 = (const float2*)g_xk2 + (size_t)z * 32 * NNDIM;

    float acc[16][4] = {};
#pragma unroll
    for (int ks = 0; ks < 4; ks++) {
        int p0 = ks << 3;
        float2 A0 = q2[(size_t)(p0 + tg) * NNDIM + nrow];
        float2 A1 = q2[(size_t)(p0 + tg) * NNDIM + nrow + 8];
        float2 A2 = q2[(size_t)(p0 + tg + 4) * NNDIM + nrow];
        float2 A3 = q2[(size_t)(p0 + tg + 4) * NNDIM + nrow + 8];
        uint32_t ahh[4] = {__float_as_uint(A0.x), __float_as_uint(A1.x),
                           __float_as_uint(A2.x), __float_as_uint(A3.x)};
        uint32_t all_[4] = {__float_as_uint(A0.y), __float_as_uint(A1.y),
                            __float_as_uint(A2.y), __float_as_uint(A3.y)};
#pragma unroll
        for (int half = 0; half < 2; half++) {
            float2 Bb0[8], Bb1[8];
#pragma unroll
            for (int j = 0; j < 8; j++) {
                int m = mb + (half * 8 + j) * 8 + gr;
                Bb0[j] = k2[(size_t)(p0 + tg) * NNDIM + m];
                Bb1[j] = k2[(size_t)(p0 + tg + 4) * NNDIM + m];
            }
#pragma unroll
            for (int j = 0; j < 8; j++) {
                int nf = half * 8 + j;
                uint32_t bh[2] = {__float_as_uint(Bb0[j].x), __float_as_uint(Bb1[j].x)};
                uint32_t bl[2] = {__float_as_uint(Bb0[j].y), __float_as_uint(Bb1[j].y)};
                mma_f16(acc[nf], ahh, bh);
                mma_f16(acc[nf], ahh, bl);
                mma_f16(acc[nf], all_, bh);
            }
        }
    }
    const unsigned FULL = 0xffffffffu;
    float m0 = -1e30f, m1 = -1e30f;
#pragma unroll
    for (int nf = 0; nf < 16; nf++) {
        m0 = fmaxf(m0, fmaxf(acc[nf][0], acc[nf][1]));
        m1 = fmaxf(m1, fmaxf(acc[nf][2], acc[nf][3]));
    }
    m0 = fmaxf(m0, __shfl_xor_sync(FULL, m0, 1));
    m0 = fmaxf(m0, __shfl_xor_sync(FULL, m0, 2));
    m1 = fmaxf(m1, __shfl_xor_sync(FULL, m1, 1));
    m1 = fmaxf(m1, __shfl_xor_sync(FULL, m1, 2));
    if (tg == 0) { redmax[r0][wm8] = m0; redmax[r0 + 8][wm8] = m1; }
    __syncthreads();
    float mx0 = -1e30f, mx1 = -1e30f;
#pragma unroll
    for (int j = 0; j < 8; j++) {
        mx0 = fmaxf(mx0, redmax[r0][j]);
        mx1 = fmaxf(mx1, redmax[r0 + 8][j]);
    }
    float s0 = 0.0f, s1 = 0.0f;
#pragma unroll
    for (int nf = 0; nf < 16; nf++) {
        acc[nf][0] = __expf(acc[nf][0] - mx0);
        acc[nf][1] = __expf(acc[nf][1] - mx0);
        acc[nf][2] = __expf(acc[nf][2] - mx1);
        acc[nf][3] = __expf(acc[nf][3] - mx1);
        s0 += acc[nf][0] + acc[nf][1];
        s1 += acc[nf][2] + acc[nf][3];
    }
    s0 += __shfl_xor_sync(FULL, s0, 1);
    s0 += __shfl_xor_sync(FULL, s0, 2);
    s1 += __shfl_xor_sync(FULL, s1, 1);
    s1 += __shfl_xor_sync(FULL, s1, 2);
    if (tg == 0) { redsum[r0][wm8] = s0; redsum[r0 + 8][wm8] = s1; }
    __syncthreads();
    float sum0 = 0.0f, sum1 = 0.0f;
#pragma unroll
    for (int j = 0; j < 8; j++) {
        sum0 += redsum[r0][j];
        sum1 += redsum[r0 + 8][j];
    }
    float inv0 = 1.0f / sum0, inv1 = 1.0f / sum1;
    float* ST = g_S + (size_t)z * NNDIM * NNDIM;
#pragma unroll
    for (int nf = 0; nf < 16; nf++) {
        int m = mb + nf * 8 + 2 * tg;
        float* c0 = ST + (size_t)m * NNDIM + nrow;
        float* c1 = c0 + NNDIM;
        c0[0] = acc[nf][0] * inv0;
        c1[0] = acc[nf][1] * inv0;
        c0[8] = acc[nf][2] * inv1;
        c1[8] = acc[nf][3] * inv1;
    }
}

// ---------------- kernel 4: cross-K renorm: fp32 in, renormalized fp16 out ----------------
__global__ void k_renorm_cvt() {
    size_t p = (size_t)blockIdx.x * 256 + threadIdx.x;   // < 8 * 262144
    int b = (int)(p >> 18);
    size_t off = (size_t)(p & 262143) << 2;              // 4 floats per thread
    const size_t ks = (size_t)NNDIM * NNDIM;
    size_t base = (size_t)b * KDIM * ks + off;
    float4 v[16];
    float4 s = make_float4(1e-9f, 1e-9f, 1e-9f, 1e-9f);
#pragma unroll
    for (int k = 0; k < 16; k++) {
        v[k] = *(const float4*)&g_S[base + (size_t)k * ks];
        s.x += v[k].x; s.y += v[k].y; s.z += v[k].z; s.w += v[k].w;
    }
    float4 inv = make_float4(1.0f / s.x, 1.0f / s.y, 1.0f / s.z, 1.0f / s.w);
#pragma unroll
    for (int k = 0; k < 16; k++) {
        __half2 h01 = __floats2half2_rn(v[k].x * inv.x, v[k].y * inv.y);
        __half2 h23 = __floats2half2_rn(v[k].z * inv.z, v[k].w * inv.w);
        uint2 o;
        o.x = *(uint32_t*)&h01;
        o.y = *(uint32_t*)&h23;
        *(uint2*)&g_Sh[base + (size_t)k * ks] = o;
    }
}

// ---------------- kernel 7: BN stats per channel ----------------
__global__ void k_stats(const float* __restrict__ gamma, const float* __restrict__ beta) {
    int c = blockIdx.x;
    int t = threadIdx.x;
    float s = 0.0f, sq = 0.0f;
    for (int b = 0; b < BB; b++) {
        const float* base = g_t + ((size_t)(b * CC + c)) * KDIM * NNDIM;
        for (int fl = t; fl < 4096; fl += 256) {
            float4 v = *(const float4*)&base[fl * 4];
            s  += v.x + v.y + v.z + v.w;
            sq += v.x * v.x + v.y * v.y + v.z * v.z + v.w * v.w;
        }
    }
    __shared__ float ss[256], sqq[256];
    ss[t] = s; sqq[t] = sq;
    __syncthreads();
    for (int o = 128; o > 0; o >>= 1) {
        if (t < o) { ss[t] += ss[t + o]; sqq[t] += sqq[t + o]; }
        __syncthreads();
    }
    if (t == 0) {
        const float cnt = 131072.0f;
        float mean = ss[0] / cnt;
        float var  = sqq[0] / cnt - mean * mean;
        float rstd = rsqrtf(var + 1e-5f);
        float a = rstd * gamma[c];
        g_a[c]  = a;
        g_b2[c] = beta[c] - mean * a;
    }
}

// ---------------- kernel 8: out = x + relu(t*a + b2), transpose [k][n]->[n][k] ----------------
__global__ void k_final(const float* __restrict__ x, float* __restrict__ out) {
    __shared__ float ts[16][68];
    int bc = blockIdx.x;
    int c  = bc & 255;
    int t  = threadIdx.x;
    float a = g_a[c], b2 = g_b2[c];
    int kk = t >> 4, n4 = (t & 15) << 2;
    int nn = t >> 2, kg = (t & 3) << 2;
    for (int n0 = 0; n0 < NNDIM; n0 += 64) {
        float4 v = *(const float4*)&g_t[((size_t)bc * KDIM + kk) * NNDIM + n0 + n4];
        *(float4*)&ts[kk][n4] = v;
        __syncthreads();
        float4 tv = make_float4(ts[kg][nn], ts[kg + 1][nn], ts[kg + 2][nn], ts[kg + 3][nn]);
        tv.x = fmaxf(tv.x * a + b2, 0.0f);
        tv.y = fmaxf(tv.y * a + b2, 0.0f);
        tv.z = fmaxf(tv.z * a + b2, 0.0f);
        tv.w = fmaxf(tv.w * a + b2, 0.0f);
        size_t idx = ((size_t)bc * NNDIM + n0 + nn) * KDIM + kg;
        float4 xv = *(const float4*)&x[idx];
        tv.x += xv.x; tv.y += xv.y; tv.z += xv.z; tv.w += xv.w;
        *(float4*)&out[idx] = tv;
        __syncthreads();
    }
}

// ---------------- launch ----------------
extern "C" void kernel_launch(void* const* d_in, const int* in_sizes, int n_in,
                              void* d_out, int out_size) {
    const float* x     = (const float*)d_in[0];
    const float* q_w   = (const float*)d_in[1];
    const float* k_w   = (const float*)d_in[2];
    const float* v_w   = (const float*)d_in[3];
    const float* v_b   = (const float*)d_in[4];
    const float* t_w   = (const float*)d_in[5];
    const float* t_b   = (const float*)d_in[6];
    const float* gamma = (const float*)d_in[7];
    const float* beta  = (const float*)d_in[8];
    float* out = (float*)d_out;

    k_concat<<<384, 256>>>(q_w, k_w, v_w);
    k_transpose_x<<<BB * CC, 256>>>(x);
    k_mma<1><<<dim3(8, 3, BB * KDIM), 256>>>(nullptr, v_b);     // q/k/v proj (+fused hi/lo pack)
    k_energy_v4<<<dim3(32, BB * KDIM), 512>>>();                // energy + softmax -> S^T fp32
    k_renorm_cvt<<<8192, 256>>>();                              // renorm fp32 -> fp16 g_Sh
    k_mma<0><<<dim3(8, 2, BB * KDIM), 256>>>(nullptr, nullptr); // x_r + (x - x_r)
    k_mma<2><<<dim3(8, 2, BB * KDIM), 256>>>(t_w, t_b);         // t projection
    k_stats<<<CC, 256>>>(gamma, beta);
    k_final<<<BB * CC, 256>>>(x, out);
}